// round 16
// baseline (speedup 1.0000x reference)
#include <cuda_runtime.h>
#include <cuda_fp16.h>
#include <math.h>
#include <stdint.h>

// ---------------- problem constants ----------------
#define B_    32
#define N_    3136
#define C_    512
#define H_    56
#define NH_   8
#define HD_   64
#define ANUM_ 49
#define SCALE_F 0.125f
#define M_    (B_ * N_)          // 100352

// ---------------- scratch ----------------
__device__ __half g_qkv16[(size_t)M_ * 1536];     // [b,n,{q|k|v},c] fp16
__device__ float  g_agent[B_ * ANUM_ * C_];
__device__ float  g_num[B_ * NH_ * ANUM_ * HD_];
__device__ float  g_den[B_ * NH_ * ANUM_];
__device__ __half g_x16[(size_t)M_ * C_];         // fp16(x)
__device__ __half g_o16[(size_t)M_ * C_];         // fp16 attention(+dwc) out
__device__ __half g_w16[1536 * 512 + 512 * 512];  // fp16 qkv_w | proj_w

// ---------------- helpers ----------------
__device__ __forceinline__ void mma_f16(float* c, const uint32_t* a, const uint32_t* b) {
    asm volatile(
        "mma.sync.aligned.m16n8k16.row.col.f32.f16.f16.f32 "
        "{%0,%1,%2,%3}, {%4,%5,%6,%7}, {%8,%9}, {%0,%1,%2,%3};\n"
        : "+f"(c[0]), "+f"(c[1]), "+f"(c[2]), "+f"(c[3])
        : "r"(a[0]), "r"(a[1]), "r"(a[2]), "r"(a[3]), "r"(b[0]), "r"(b[1]));
}

__device__ __forceinline__ void ldsm4(uint32_t* r, uint32_t addr) {
    asm volatile("ldmatrix.sync.aligned.m8n8.x4.shared.b16 {%0,%1,%2,%3}, [%4];"
                 : "=r"(r[0]), "=r"(r[1]), "=r"(r[2]), "=r"(r[3]) : "r"(addr));
}

__device__ __forceinline__ void ldsm2t(uint32_t* r, uint32_t addr) {
    asm volatile("ldmatrix.sync.aligned.m8n8.x2.trans.shared.b16 {%0,%1}, [%2];"
                 : "=r"(r[0]), "=r"(r[1]) : "r"(addr));
}

__device__ __forceinline__ void ldsm2(uint32_t* r, uint32_t addr) {
    asm volatile("ldmatrix.sync.aligned.m8n8.x2.shared.b16 {%0,%1}, [%2];"
                 : "=r"(r[0]), "=r"(r[1]) : "r"(addr));
}

__device__ __forceinline__ uint32_t smem_u32(const void* p) {
    uint32_t a;
    asm("{ .reg .u64 t; cvta.to.shared.u64 t, %1; cvt.u32.u64 %0, t; }" : "=r"(a) : "l"(p));
    return a;
}

__device__ __forceinline__ void cp16(uint32_t dst, const void* src) {
    asm volatile("cp.async.cg.shared.global [%0], [%1], 16;" :: "r"(dst), "l"(src));
}

// ---------------- fp32 -> fp16 pre-convert ----------------
__global__ void cvt_f16(const float* __restrict__ src, __half* __restrict__ dst, int n4)
{
    const int i = blockIdx.x * 256 + threadIdx.x;
    if (i < n4) {
        float4 v = ((const float4*)src)[i];
        __half2 h0 = __floats2half2_rn(v.x, v.y);
        __half2 h1 = __floats2half2_rn(v.z, v.w);
        uint2 u;
        u.x = *(uint32_t*)&h0;
        u.y = *(uint32_t*)&h1;
        ((uint2*)dst)[i] = u;
    }
}

// ---------------- pipelined fp16 tensor-core GEMM (BK=32, 4-stage ring) ---------
// FROZEN (validated R15). C[M,N] = A[M,K] * B[N,K]^T (+bias).
#define HSTRB  80u
#define GBK    32
#define GSTG   4
#define HSTAGE (128u * HSTRB)
#define GH_SMEM (GSTG * 2 * 10240 + 512)

__global__ void __launch_bounds__(256, 2)
gemm_h(const __half* __restrict__ A, const __half* __restrict__ Bw,
       float* __restrict__ C, __half* __restrict__ C16,
       const float* __restrict__ bias,
       int K, int lda, int ldb, int ldc)
{
    extern __shared__ char smemc[];
    float* bsh = (float*)(smemc + GSTG * 2 * 10240);

    const uint32_t aSmem = smem_u32(smemc);
    const uint32_t bSmem = aSmem + GSTG * HSTAGE;

    const int tid = threadIdx.x;
    const int wid = tid >> 5, lane = tid & 31;
    const int g = lane >> 2, t = lane & 3;
    const int wm = (wid >> 2) * 64;
    const int wn = (wid & 3) * 32;
    const long bm0 = (long)blockIdx.y * 128;
    const long bn0 = (long)blockIdx.x * 128;

    const int lr = tid >> 2;
    const int lj = tid & 3;

    if (tid < 128) bsh[tid] = bias ? bias[bn0 + tid] : 0.f;

    const __half* Ag = A + (bm0 + lr) * (long)lda + lj * 8;
    const __half* Bg = Bw + (bn0 + lr) * (long)ldb + lj * 8;
    const long a64 = 64l * lda, b64 = 64l * ldb;
    const uint32_t soff = (uint32_t)lr * HSTRB + (uint32_t)lj * 16u;

    auto load_stage = [&](int s) {
        const int buf = s % GSTG;
        const __half* Ap = Ag + s * GBK;
        const __half* Bp = Bg + s * GBK;
        const uint32_t bofs = (uint32_t)buf * HSTAGE + soff;
        cp16(aSmem + bofs, Ap);
        cp16(aSmem + bofs + 64u * HSTRB, Ap + a64);
        cp16(bSmem + bofs, Bp);
        cp16(bSmem + bofs + 64u * HSTRB, Bp + b64);
        asm volatile("cp.async.commit_group;" ::: "memory");
    };

    const int aTile = lane >> 3;
    const uint32_t aLane =
        (uint32_t)(((aTile & 1) * 8 + (lane & 7)) * HSTRB + (aTile >> 1) * 16);
    const uint32_t bLane =
        (uint32_t)((lane & 7) * HSTRB + ((lane >> 3) & 1) * 16);

    float acc[4][4][4];
#pragma unroll
    for (int i = 0; i < 4; ++i)
#pragma unroll
        for (int j = 0; j < 4; ++j)
#pragma unroll
            for (int q = 0; q < 4; ++q) acc[i][j][q] = 0.f;

    const int nkt = K / GBK;
    load_stage(0);
    load_stage(1);
    load_stage(2);

    for (int kt = 0; kt < nkt; ++kt) {
        asm volatile("cp.async.wait_group 2;" ::: "memory");
        __syncthreads();
        const uint32_t aCur = aSmem + (uint32_t)(kt % GSTG) * HSTAGE + aLane;
        const uint32_t bCur = bSmem + (uint32_t)(kt % GSTG) * HSTAGE + bLane;

#pragma unroll
        for (int ks = 0; ks < 2; ++ks) {
            uint32_t af[4][4], bf[4][2];
#pragma unroll
            for (int mf = 0; mf < 4; ++mf)
                ldsm4(af[mf], aCur + (uint32_t)(wm + mf * 16) * HSTRB + ks * 32u);
#pragma unroll
            for (int nf = 0; nf < 4; ++nf)
                ldsm2(bf[nf], bCur + (uint32_t)(wn + nf * 8) * HSTRB + ks * 32u);
#pragma unroll
            for (int mf = 0; mf < 4; ++mf)
#pragma unroll
                for (int nf = 0; nf < 4; ++nf)
                    mma_f16(acc[mf][nf], af[mf], bf[nf]);
        }

        if (kt + 3 < nkt) load_stage(kt + 3);
        else asm volatile("cp.async.commit_group;" ::: "memory");
    }

#pragma unroll
    for (int mf = 0; mf < 4; ++mf) {
        const long row = bm0 + wm + mf * 16 + g;
#pragma unroll
        for (int nf = 0; nf < 4; ++nf) {
            const int col = wn + nf * 8 + 2 * t;
            float2 v0, v1;
            v0.x = acc[mf][nf][0] + bsh[col];
            v0.y = acc[mf][nf][1] + bsh[col + 1];
            v1.x = acc[mf][nf][2] + bsh[col];
            v1.y = acc[mf][nf][3] + bsh[col + 1];
            if (C) {
                *(float2*)(C + row * (long)ldc + bn0 + col) = v0;
                *(float2*)(C + (row + 8) * (long)ldc + bn0 + col) = v1;
            }
            if (C16) {
                __half2 h0 = __floats2half2_rn(v0.x, v0.y);
                __half2 h1 = __floats2half2_rn(v1.x, v1.y);
                *(uint32_t*)(C16 + row * (long)ldc + bn0 + col) = *(uint32_t*)&h0;
                *(uint32_t*)(C16 + (row + 8) * (long)ldc + bn0 + col) = *(uint32_t*)&h1;
            }
        }
    }
}

// ---------------- agent pooling (fp16 source, fp32 accumulate) ----------------
__global__ void __launch_bounds__(256)
pool_q16()
{
    const int bp = blockIdx.x;
    const int b = bp / ANUM_, p = bp % ANUM_;
    const int ph = p / 7, pw = p % 7;
    const int c2 = threadIdx.x;
    float sx = 0.f, sy = 0.f;
#pragma unroll
    for (int iy = 0; iy < 8; ++iy)
#pragma unroll
        for (int ix = 0; ix < 8; ++ix) {
            const int n = (ph * 8 + iy) * H_ + pw * 8 + ix;
            const __half2 v = *(const __half2*)&g_qkv16[((size_t)(b * N_ + n)) * 1536 + 2 * c2];
            const float2 f = __half22float2(v);
            sx += f.x; sy += f.y;
        }
    float2 o;
    o.x = sx * 0.015625f;
    o.y = sy * 0.015625f;
    *(float2*)&g_agent[((size_t)b * ANUM_ + p) * C_ + 2 * c2] = o;
}

__global__ void zero_acc()
{
    const int i = blockIdx.x * 256 + threadIdx.x;
    if (i < B_ * NH_ * ANUM_ * HD_) g_num[i] = 0.f;
    if (i < B_ * NH_ * ANUM_)       g_den[i] = 0.f;
}

// ---------------- agent attention via tensor cores (8 warps: N-slices of 8) -----
#define AKROW 144u
#define AG_OFF  0u
#define W_OFF   9216u
#define KS_OFF  18432u
#define VS_OFF  36864u
#define DEN_OFF 55296u
#define AK_SMEM 55552

__global__ void __launch_bounds__(256)
agent_kv_mma()
{
    extern __shared__ char sm[];
    const uint32_t sb = smem_u32(sm);
    float* den_s = (float*)(sm + DEN_OFF);
    __half* ag16 = (__half*)(sm + AG_OFF);
    __half* Wsm  = (__half*)(sm + W_OFF);

    const int bh = blockIdx.x;
    const int part = blockIdx.y;
    const int b = bh >> 3, h = bh & 7;
    const int tid = threadIdx.x;
    const int wid = tid >> 5, lane = tid & 31;
    const int g = lane >> 2, t = lane & 3;
    const int wtok = wid * 8;            // phase1: 8 tokens per warp
    const int wdim = wid * 8;            // phase2: 8 dims per warp

    for (int i = tid; i < 64 * 64; i += 256) {
        const int a = i >> 6, d = i & 63;
        float v = 0.f;
        if (a < ANUM_)
            v = g_agent[((size_t)(b * ANUM_ + a)) * C_ + h * HD_ + d] * SCALE_F;
        ag16[a * 72 + d] = __float2half(v);
    }
    if (tid < 64) den_s[tid] = 0.f;
    __syncthreads();

    const int aTile = lane >> 3;
    const uint32_t aLane =
        (uint32_t)(((aTile & 1) * 8 + (lane & 7)) * AKROW + (aTile >> 1) * 16);
    const uint32_t bLane =
        (uint32_t)((lane & 7) * AKROW + ((lane >> 3) & 1) * 16);

    uint32_t agF[4][4][4];
#pragma unroll
    for (int mf = 0; mf < 4; ++mf)
#pragma unroll
        for (int ks = 0; ks < 4; ++ks)
            ldsm4(agF[mf][ks], sb + AG_OFF + aLane + (uint32_t)(mf * 16) * AKROW + ks * 32u);

    const int ntok0 = part * 448;
    auto load_tile = [&](int tt) {
        const uint32_t buf = (uint32_t)(tt & 1) * 9216u;
#pragma unroll
        for (int it = 0; it < 2; ++it) {
            const int i = tid + it * 256;
            const int r = i >> 3, cch = i & 7;
            const __half* src =
                g_qkv16 + ((size_t)(b * N_ + ntok0 + tt * 64 + r)) * 1536 + 512 + h * HD_ + cch * 8;
            cp16(sb + KS_OFF + buf + (uint32_t)r * AKROW + cch * 16u, src);
            cp16(sb + VS_OFF + buf + (uint32_t)r * AKROW + cch * 16u, src + 512);
        }
        asm volatile("cp.async.commit_group;" ::: "memory");
    };

    float acc[4][4];
#pragma unroll
    for (int i = 0; i < 4; ++i)
#pragma unroll
        for (int q = 0; q < 4; ++q) acc[i][q] = 0.f;

    load_tile(0);

    for (int tt = 0; tt < 7; ++tt) {
        asm volatile("cp.async.wait_group 0;" ::: "memory");
        __syncthreads();
        const uint32_t buf = (uint32_t)(tt & 1) * 9216u;

        // phase 1: logits for this warp's 8 tokens
        float c1[4][4];
#pragma unroll
        for (int i = 0; i < 4; ++i)
#pragma unroll
            for (int q = 0; q < 4; ++q) c1[i][q] = 0.f;

#pragma unroll
        for (int ks = 0; ks < 4; ++ks) {
            uint32_t kF[2];
            ldsm2(kF, sb + KS_OFF + buf + bLane + (uint32_t)wtok * AKROW + ks * 32u);
#pragma unroll
            for (int mf = 0; mf < 4; ++mf)
                mma_f16(c1[mf], agF[mf][ks], kF);
        }

        if (tt + 1 < 7) load_tile(tt + 1);
        else asm volatile("cp.async.commit_group;" ::: "memory");

        // exp, den partials, W store
#pragma unroll
        for (int mf = 0; mf < 4; ++mf) {
            float e[4];
#pragma unroll
            for (int q = 0; q < 4; ++q) e[q] = expf(c1[mf][q]);
            float d0 = e[0] + e[1];
            float d1 = e[2] + e[3];
            d0 += __shfl_xor_sync(0xffffffff, d0, 1);
            d0 += __shfl_xor_sync(0xffffffff, d0, 2);
            d1 += __shfl_xor_sync(0xffffffff, d1, 1);
            d1 += __shfl_xor_sync(0xffffffff, d1, 2);
            const int rowA = mf * 16 + g, rowB = rowA + 8;
            if (t == 0) {
                atomicAdd(&den_s[rowA], d0);
                atomicAdd(&den_s[rowB], d1);
            }
            const int col = wtok + 2 * t;
            __half2 h0 = __floats2half2_rn(e[0], e[1]);
            __half2 h1 = __floats2half2_rn(e[2], e[3]);
            *(uint32_t*)&Wsm[rowA * 72 + col] = *(uint32_t*)&h0;
            *(uint32_t*)&Wsm[rowB * 72 + col] = *(uint32_t*)&h1;
        }
        __syncthreads();

        // phase 2: agent_v += W @ V for this warp's 8 dims
#pragma unroll
        for (int ks = 0; ks < 4; ++ks) {
            uint32_t vF[2];
            ldsm2t(vF, sb + VS_OFF + buf +
                   (uint32_t)(ks * 16 + (lane & 15)) * AKROW + (uint32_t)wdim * 2u);
#pragma unroll
            for (int mf = 0; mf < 4; ++mf) {
                uint32_t wF[4];
                ldsm4(wF, sb + W_OFF + aLane + (uint32_t)(mf * 16) * AKROW + ks * 32u);
                mma_f16(acc[mf], wF, vF);
            }
        }
        __syncthreads();
    }

    if (tid < ANUM_) atomicAdd(&g_den[bh * ANUM_ + tid], den_s[tid]);
#pragma unroll
    for (int mf = 0; mf < 4; ++mf) {
        const int rowA = mf * 16 + g, rowB = rowA + 8;
        const int dim = wdim + 2 * t;
        if (rowA < ANUM_) {
            float* p = &g_num[(((size_t)bh * ANUM_) + rowA) * HD_ + dim];
            atomicAdd(p, acc[mf][0]);
            atomicAdd(p + 1, acc[mf][1]);
        }
        if (rowB < ANUM_) {
            float* p = &g_num[(((size_t)bh * ANUM_) + rowB) * HD_ + dim];
            atomicAdd(p, acc[mf][2]);
            atomicAdd(p + 1, acc[mf][3]);
        }
    }
}

// ---------------- q attention via tensor cores (8 warps: N-slices of 8) ---------
#define QA_AG   0u
#define QA_AV   9216u
#define QA_W    18432u
#define QA_Q    27648u
#define QA_DEN  46080u                 // float[8][64]
#define QA_SMEM 48128

__global__ void __launch_bounds__(256)
q_attn_mma()
{
    extern __shared__ char sm[];
    const uint32_t sb = smem_u32(sm);
    __half* ag16 = (__half*)(sm + QA_AG);
    __half* av16 = (__half*)(sm + QA_AV);
    __half* Wsm  = (__half*)(sm + QA_W);
    float* den_s = (float*)(sm + QA_DEN);

    const int bh = blockIdx.x;
    const int part = blockIdx.y;
    const int b = bh >> 3, h = bh & 7;
    const int tid = threadIdx.x;
    const int wid = tid >> 5, lane = tid & 31;
    const int g = lane >> 2, t = lane & 3;
    const int wagent = wid * 8;          // phase1: 8 agents per warp
    const int wdim = wid * 8;            // phase2: 8 dims per warp

    for (int i = tid; i < 64 * 64; i += 256) {
        const int a = i >> 6, d = i & 63;
        float va = 0.f, vv = 0.f;
        if (a < ANUM_) {
            va = g_agent[((size_t)(b * ANUM_ + a)) * C_ + h * HD_ + d] * SCALE_F;
            vv = g_num[(((size_t)bh * ANUM_) + a) * HD_ + d] / g_den[bh * ANUM_ + a];
        }
        ag16[a * 72 + d] = __float2half(va);
        av16[a * 72 + d] = __float2half(vv);
    }
    __syncthreads();

    const int aTile = lane >> 3;
    const uint32_t aLane =
        (uint32_t)(((aTile & 1) * 8 + (lane & 7)) * AKROW + (aTile >> 1) * 16);
    const uint32_t bLane =
        (uint32_t)((lane & 7) * AKROW + ((lane >> 3) & 1) * 16);

    // hoist ag B-frags (this warp's 8 agents) and av^T B-frags (8 dims)
    uint32_t agB[4][2];
#pragma unroll
    for (int ks = 0; ks < 4; ++ks)
        ldsm2(agB[ks], sb + QA_AG + bLane + (uint32_t)wagent * AKROW + ks * 32u);
    uint32_t avB[4][2];
#pragma unroll
    for (int ks = 0; ks < 4; ++ks)
        ldsm2t(avB[ks], sb + QA_AV +
               (uint32_t)(ks * 16 + (lane & 15)) * AKROW + (uint32_t)wdim * 2u);

    const int ntok0 = part * 448;
    auto load_tile = [&](int tt) {
        const uint32_t buf = (uint32_t)(tt & 1) * 9216u;
#pragma unroll
        for (int it = 0; it < 2; ++it) {
            const int i = tid + it * 256;
            const int r = i >> 3, cch = i & 7;
            const __half* src =
                g_qkv16 + ((size_t)(b * N_ + ntok0 + tt * 64 + r)) * 1536 + h * HD_ + cch * 8;
            cp16(sb + QA_Q + buf + (uint32_t)r * AKROW + cch * 16u, src);
        }
        asm volatile("cp.async.commit_group;" ::: "memory");
    };

    load_tile(0);

    for (int tt = 0; tt < 7; ++tt) {
        asm volatile("cp.async.wait_group 0;" ::: "memory");
        __syncthreads();
        const uint32_t buf = (uint32_t)(tt & 1) * 9216u;

        // phase 1: logits (64 tok x this warp's 8 agents)
        float c1[4][4];
#pragma unroll
        for (int i = 0; i < 4; ++i)
#pragma unroll
            for (int q = 0; q < 4; ++q) c1[i][q] = 0.f;

#pragma unroll
        for (int ks = 0; ks < 4; ++ks) {
            uint32_t qf[4][4];
#pragma unroll
            for (int mf = 0; mf < 4; ++mf)
                ldsm4(qf[mf], sb + QA_Q + buf + aLane +
                      (uint32_t)(mf * 16) * AKROW + ks * 32u);
#pragma unroll
            for (int mf = 0; mf < 4; ++mf)
                mma_f16(c1[mf], qf[mf], agB[ks]);
        }

        if (tt + 1 < 7) load_tile(tt + 1);
        else asm volatile("cp.async.commit_group;" ::: "memory");

        // exp, per-warp den partials, W store
#pragma unroll
        for (int mf = 0; mf < 4; ++mf) {
            float e[4];
#pragma unroll
            for (int q = 0; q < 4; ++q) e[q] = expf(c1[mf][q]);
            float d0 = e[0] + e[1];
            float d1 = e[2] + e[3];
            d0 += __shfl_xor_sync(0xffffffff, d0, 1);
            d0 += __shfl_xor_sync(0xffffffff, d0, 2);
            d1 += __shfl_xor_sync(0xffffffff, d1, 1);
            d1 += __shfl_xor_sync(0xffffffff, d1, 2);
            const int rowA = mf * 16 + g, rowB = rowA + 8;
            if (t == 0) {
                den_s[wid * 64 + rowA] = d0;
                den_s[wid * 64 + rowB] = d1;
            }
            const int col = wagent + 2 * t;
            __half2 h0 = __floats2half2_rn(e[0], e[1]);
            __half2 h1 = __floats2half2_rn(e[2], e[3]);
            *(uint32_t*)&Wsm[rowA * 72 + col] = *(uint32_t*)&h0;
            *(uint32_t*)&Wsm[rowB * 72 + col] = *(uint32_t*)&h1;
        }
        __syncthreads();

        // phase 2: out = W @ av for this warp's 8 dims
        float acc[4][4];
#pragma unroll
        for (int i = 0; i < 4; ++i)
#pragma unroll
            for (int q = 0; q < 4; ++q) acc[i][q] = 0.f;

#pragma unroll
        for (int ks = 0; ks < 4; ++ks) {
#pragma unroll
            for (int mf = 0; mf < 4; ++mf) {
                uint32_t wF[4];
                ldsm4(wF, sb + QA_W + aLane + (uint32_t)(mf * 16) * AKROW + ks * 32u);
                mma_f16(acc[mf], wF, avB[ks]);
            }
        }

        // epilogue: normalize (sum 8 partials, -15 pad correction), write fp16
#pragma unroll
        for (int mf = 0; mf < 4; ++mf) {
            const int rowA = mf * 16 + g, rowB = rowA + 8;
            float sA = -15.f, sB = -15.f;
#pragma unroll
            for (int w = 0; w < 8; ++w) {
                sA += den_s[w * 64 + rowA];
                sB += den_s[w * 64 + rowB];
            }
            const float invA = 1.f / sA;
            const float invB = 1.f / sB;
            const long tokA = (long)(b * N_ + ntok0 + tt * 64 + rowA);
            const long tokB = (long)(b * N_ + ntok0 + tt * 64 + rowB);
            const int col = h * HD_ + wdim + 2 * t;
            __half2 h0 = __floats2half2_rn(acc[mf][0] * invA, acc[mf][1] * invA);
            __half2 h1 = __floats2half2_rn(acc[mf][2] * invB, acc[mf][3] * invB);
            *(uint32_t*)&g_o16[tokA * C_ + col] = *(uint32_t*)&h0;
            *(uint32_t*)&g_o16[tokB * C_ + col] = *(uint32_t*)&h1;
        }
        __syncthreads();
    }
}

// ---------------- depthwise 3x3 conv on v16, += into g_o16 (with bias) ----------
__global__ void __launch_bounds__(256)
dwc16(const float* __restrict__ w, const float* __restrict__ bias)
{
    __shared__ float ws[C_ * 9];
    __shared__ float bs[C_];
    const int b = blockIdx.x, y = blockIdx.y;
    const int tid = threadIdx.x;
    for (int i = tid; i < C_ * 9; i += 256) ws[i] = w[i];
    for (int i = tid; i < C_; i += 256) bs[i] = bias[i];
    __syncthreads();

    for (int i = tid; i < H_ * 64; i += 256) {
        const int x = i >> 6;
        const int c8 = (i & 63) * 8;
        float a[8];
#pragma unroll
        for (int j = 0; j < 8; ++j) a[j] = bs[c8 + j];

#pragma unroll
        for (int ky = 0; ky < 3; ++ky) {
            const int yy = y + ky - 1;
            if (yy < 0 || yy >= H_) continue;
#pragma unroll
            for (int kx = 0; kx < 3; ++kx) {
                const int xx = x + kx - 1;
                if (xx < 0 || xx >= H_) continue;
                const int tap = ky * 3 + kx;
                const uint4 v = *(const uint4*)&g_qkv16[((size_t)(b * N_ + yy * H_ + xx)) * 1536 + 1024 + c8];
                const __half2* vh = (const __half2*)&v;
#pragma unroll
                for (int j2 = 0; j2 < 4; ++j2) {
                    const float2 f = __half22float2(vh[j2]);
                    a[j2 * 2 + 0] += f.x * ws[(c8 + j2 * 2 + 0) * 9 + tap];
                    a[j2 * 2 + 1] += f.y * ws[(c8 + j2 * 2 + 1) * 9 + tap];
                }
            }
        }

        __half* op = &g_o16[((size_t)(b * N_ + y * H_ + x)) * C_ + c8];
        uint4 o = *(uint4*)op;
        __half2* oh = (__half2*)&o;
#pragma unroll
        for (int j2 = 0; j2 < 4; ++j2) {
            float2 f = __half22float2(oh[j2]);
            f.x += a[j2 * 2 + 0];
            f.y += a[j2 * 2 + 1];
            oh[j2] = __floats2half2_rn(f.x, f.y);
        }
        *(uint4*)op = o;
    }
}

// ---------------- launch ----------------
extern "C" void kernel_launch(void* const* d_in, const int* in_sizes, int n_in,
                              void* d_out, int out_size)
{
    const float* x      = (const float*)d_in[0];
    const float* qkv_w  = (const float*)d_in[1];
    const float* proj_w = (const float*)d_in[2];
    const float* proj_b = (const float*)d_in[3];
    const float* dwc_w  = (const float*)d_in[4];
    const float* dwc_b  = (const float*)d_in[5];
    float* out = (float*)d_out;

    __half *p_qkv16 = nullptr, *p_x16 = nullptr, *p_o16 = nullptr, *p_w16 = nullptr;
    cudaGetSymbolAddress((void**)&p_qkv16, g_qkv16);
    cudaGetSymbolAddress((void**)&p_x16, g_x16);
    cudaGetSymbolAddress((void**)&p_o16, g_o16);
    cudaGetSymbolAddress((void**)&p_w16, g_w16);

    cudaFuncSetAttribute(gemm_h, cudaFuncAttributeMaxDynamicSharedMemorySize, GH_SMEM);
    cudaFuncSetAttribute(agent_kv_mma, cudaFuncAttributeMaxDynamicSharedMemorySize, AK_SMEM);
    cudaFuncSetAttribute(q_attn_mma, cudaFuncAttributeMaxDynamicSharedMemorySize, QA_SMEM);

    // 0. pre-convert inputs to fp16
    cvt_f16<<<(M_ * C_ / 4 + 255) / 256, 256>>>(x, p_x16, M_ * C_ / 4);
    cvt_f16<<<(1536 * 512 / 4 + 255) / 256, 256>>>(qkv_w, p_w16, 1536 * 512 / 4);
    cvt_f16<<<(512 * 512 / 4 + 255) / 256, 256>>>(proj_w, p_w16 + 1536 * 512, 512 * 512 / 4);

    // 1. QKV projection -> g_qkv16 (fp16 only)
    gemm_h<<<dim3(1536 / 128, M_ / 128), 256, GH_SMEM>>>(p_x16, p_w16, nullptr, p_qkv16, nullptr, 512, 512, 512, 1536);
    // 2. zero agent-attn accumulators
    zero_acc<<<(B_ * NH_ * ANUM_ * HD_ + 255) / 256, 256>>>();
    // 3. agent pooling (fp16 source)
    pool_q16<<<B_ * ANUM_, 256>>>();
    // 4. agent attention (tensor cores, 8 warps)
    agent_kv_mma<<<dim3(B_ * NH_, 7), 256, AK_SMEM>>>();
    // 5. q attention (tensor cores, 8 warps) -> g_o16
    q_attn_mma<<<dim3(B_ * NH_, 7), 256, QA_SMEM>>>();
    // 6. depthwise conv on v16, += into g_o16 (with bias)
    dwc16<<<dim3(B_, H_), 256>>>(dwc_w, dwc_b);
    // 7. output projection (+bias) -> d_out (fp32)
    gemm_h<<<dim3(512 / 128, M_ / 128), 256, GH_SMEM>>>(p_o16, p_w16 + 1536 * 512, out, nullptr, proj_b, 512, 512, 512, 512);
}

// round 17
// speedup vs baseline: 1.0547x; 1.0547x over previous
#include <cuda_runtime.h>
#include <cuda_fp16.h>
#include <math.h>
#include <stdint.h>

// ---------------- problem constants ----------------
#define B_    32
#define N_    3136
#define C_    512
#define H_    56
#define NH_   8
#define HD_   64
#define ANUM_ 49
#define SCALE_F 0.125f
#define M_    (B_ * N_)          // 100352

// ---------------- scratch ----------------
__device__ __half g_qkv16[(size_t)M_ * 1536];     // [b,n,{q|k|v},c] fp16
__device__ float  g_agent[B_ * ANUM_ * C_];
__device__ float  g_num[B_ * NH_ * ANUM_ * HD_];
__device__ float  g_den[B_ * NH_ * ANUM_];
__device__ __half g_x16[(size_t)M_ * C_];         // fp16(x)
__device__ __half g_o16[(size_t)M_ * C_];         // fp16 attention(+dwc) out
__device__ __half g_w16[1536 * 512 + 512 * 512];  // fp16 qkv_w | proj_w

// ---------------- helpers ----------------
__device__ __forceinline__ void mma_f16(float* c, const uint32_t* a, const uint32_t* b) {
    asm volatile(
        "mma.sync.aligned.m16n8k16.row.col.f32.f16.f16.f32 "
        "{%0,%1,%2,%3}, {%4,%5,%6,%7}, {%8,%9}, {%0,%1,%2,%3};\n"
        : "+f"(c[0]), "+f"(c[1]), "+f"(c[2]), "+f"(c[3])
        : "r"(a[0]), "r"(a[1]), "r"(a[2]), "r"(a[3]), "r"(b[0]), "r"(b[1]));
}

__device__ __forceinline__ void ldsm4(uint32_t* r, uint32_t addr) {
    asm volatile("ldmatrix.sync.aligned.m8n8.x4.shared.b16 {%0,%1,%2,%3}, [%4];"
                 : "=r"(r[0]), "=r"(r[1]), "=r"(r[2]), "=r"(r[3]) : "r"(addr));
}

__device__ __forceinline__ void ldsm4t(uint32_t* r, uint32_t addr) {
    asm volatile("ldmatrix.sync.aligned.m8n8.x4.trans.shared.b16 {%0,%1,%2,%3}, [%4];"
                 : "=r"(r[0]), "=r"(r[1]), "=r"(r[2]), "=r"(r[3]) : "r"(addr));
}

__device__ __forceinline__ void ldsm2(uint32_t* r, uint32_t addr) {
    asm volatile("ldmatrix.sync.aligned.m8n8.x2.shared.b16 {%0,%1}, [%2];"
                 : "=r"(r[0]), "=r"(r[1]) : "r"(addr));
}

__device__ __forceinline__ uint32_t smem_u32(const void* p) {
    uint32_t a;
    asm("{ .reg .u64 t; cvta.to.shared.u64 t, %1; cvt.u32.u64 %0, t; }" : "=r"(a) : "l"(p));
    return a;
}

__device__ __forceinline__ void cp16(uint32_t dst, const void* src) {
    asm volatile("cp.async.cg.shared.global [%0], [%1], 16;" :: "r"(dst), "l"(src));
}

// fast exp: logits are tiny (|x| < ~0.5), __expf (ex2.approx) rel err ~1e-6
__device__ __forceinline__ float fexp(float x) { return __expf(x); }

// ---------------- fp32 -> fp16 pre-convert ----------------
__global__ void cvt_f16(const float* __restrict__ src, __half* __restrict__ dst, int n4)
{
    const int i = blockIdx.x * 256 + threadIdx.x;
    if (i < n4) {
        float4 v = ((const float4*)src)[i];
        __half2 h0 = __floats2half2_rn(v.x, v.y);
        __half2 h1 = __floats2half2_rn(v.z, v.w);
        uint2 u;
        u.x = *(uint32_t*)&h0;
        u.y = *(uint32_t*)&h1;
        ((uint2*)dst)[i] = u;
    }
}

// ---------------- pipelined fp16 tensor-core GEMM (BK=32, 4-stage ring) ---------
// FROZEN (validated R15). C[M,N] = A[M,K] * B[N,K]^T (+bias).
#define HSTRB  80u
#define GBK    32
#define GSTG   4
#define HSTAGE (128u * HSTRB)
#define GH_SMEM (GSTG * 2 * 10240 + 512)

__global__ void __launch_bounds__(256, 2)
gemm_h(const __half* __restrict__ A, const __half* __restrict__ Bw,
       float* __restrict__ C, __half* __restrict__ C16,
       const float* __restrict__ bias,
       int K, int lda, int ldb, int ldc)
{
    extern __shared__ char smemc[];
    float* bsh = (float*)(smemc + GSTG * 2 * 10240);

    const uint32_t aSmem = smem_u32(smemc);
    const uint32_t bSmem = aSmem + GSTG * HSTAGE;

    const int tid = threadIdx.x;
    const int wid = tid >> 5, lane = tid & 31;
    const int g = lane >> 2, t = lane & 3;
    const int wm = (wid >> 2) * 64;
    const int wn = (wid & 3) * 32;
    const long bm0 = (long)blockIdx.y * 128;
    const long bn0 = (long)blockIdx.x * 128;

    const int lr = tid >> 2;
    const int lj = tid & 3;

    if (tid < 128) bsh[tid] = bias ? bias[bn0 + tid] : 0.f;

    const __half* Ag = A + (bm0 + lr) * (long)lda + lj * 8;
    const __half* Bg = Bw + (bn0 + lr) * (long)ldb + lj * 8;
    const long a64 = 64l * lda, b64 = 64l * ldb;
    const uint32_t soff = (uint32_t)lr * HSTRB + (uint32_t)lj * 16u;

    auto load_stage = [&](int s) {
        const int buf = s % GSTG;
        const __half* Ap = Ag + s * GBK;
        const __half* Bp = Bg + s * GBK;
        const uint32_t bofs = (uint32_t)buf * HSTAGE + soff;
        cp16(aSmem + bofs, Ap);
        cp16(aSmem + bofs + 64u * HSTRB, Ap + a64);
        cp16(bSmem + bofs, Bp);
        cp16(bSmem + bofs + 64u * HSTRB, Bp + b64);
        asm volatile("cp.async.commit_group;" ::: "memory");
    };

    const int aTile = lane >> 3;
    const uint32_t aLane =
        (uint32_t)(((aTile & 1) * 8 + (lane & 7)) * HSTRB + (aTile >> 1) * 16);
    const uint32_t bLane =
        (uint32_t)((lane & 7) * HSTRB + ((lane >> 3) & 1) * 16);

    float acc[4][4][4];
#pragma unroll
    for (int i = 0; i < 4; ++i)
#pragma unroll
        for (int j = 0; j < 4; ++j)
#pragma unroll
            for (int q = 0; q < 4; ++q) acc[i][j][q] = 0.f;

    const int nkt = K / GBK;
    load_stage(0);
    load_stage(1);
    load_stage(2);

    for (int kt = 0; kt < nkt; ++kt) {
        asm volatile("cp.async.wait_group 2;" ::: "memory");
        __syncthreads();
        const uint32_t aCur = aSmem + (uint32_t)(kt % GSTG) * HSTAGE + aLane;
        const uint32_t bCur = bSmem + (uint32_t)(kt % GSTG) * HSTAGE + bLane;

#pragma unroll
        for (int ks = 0; ks < 2; ++ks) {
            uint32_t af[4][4], bf[4][2];
#pragma unroll
            for (int mf = 0; mf < 4; ++mf)
                ldsm4(af[mf], aCur + (uint32_t)(wm + mf * 16) * HSTRB + ks * 32u);
#pragma unroll
            for (int nf = 0; nf < 4; ++nf)
                ldsm2(bf[nf], bCur + (uint32_t)(wn + nf * 8) * HSTRB + ks * 32u);
#pragma unroll
            for (int mf = 0; mf < 4; ++mf)
#pragma unroll
                for (int nf = 0; nf < 4; ++nf)
                    mma_f16(acc[mf][nf], af[mf], bf[nf]);
        }

        if (kt + 3 < nkt) load_stage(kt + 3);
        else asm volatile("cp.async.commit_group;" ::: "memory");
    }

#pragma unroll
    for (int mf = 0; mf < 4; ++mf) {
        const long row = bm0 + wm + mf * 16 + g;
#pragma unroll
        for (int nf = 0; nf < 4; ++nf) {
            const int col = wn + nf * 8 + 2 * t;
            float2 v0, v1;
            v0.x = acc[mf][nf][0] + bsh[col];
            v0.y = acc[mf][nf][1] + bsh[col + 1];
            v1.x = acc[mf][nf][2] + bsh[col];
            v1.y = acc[mf][nf][3] + bsh[col + 1];
            if (C) {
                *(float2*)(C + row * (long)ldc + bn0 + col) = v0;
                *(float2*)(C + (row + 8) * (long)ldc + bn0 + col) = v1;
            }
            if (C16) {
                __half2 h0 = __floats2half2_rn(v0.x, v0.y);
                __half2 h1 = __floats2half2_rn(v1.x, v1.y);
                *(uint32_t*)(C16 + row * (long)ldc + bn0 + col) = *(uint32_t*)&h0;
                *(uint32_t*)(C16 + (row + 8) * (long)ldc + bn0 + col) = *(uint32_t*)&h1;
            }
        }
    }
}

// ---------------- agent pooling (fp16 source, fp32 accumulate) ----------------
__global__ void __launch_bounds__(256)
pool_q16()
{
    const int bp = blockIdx.x;
    const int b = bp / ANUM_, p = bp % ANUM_;
    const int ph = p / 7, pw = p % 7;
    const int c2 = threadIdx.x;
    float sx = 0.f, sy = 0.f;
#pragma unroll
    for (int iy = 0; iy < 8; ++iy)
#pragma unroll
        for (int ix = 0; ix < 8; ++ix) {
            const int n = (ph * 8 + iy) * H_ + pw * 8 + ix;
            const __half2 v = *(const __half2*)&g_qkv16[((size_t)(b * N_ + n)) * 1536 + 2 * c2];
            const float2 f = __half22float2(v);
            sx += f.x; sy += f.y;
        }
    float2 o;
    o.x = sx * 0.015625f;
    o.y = sy * 0.015625f;
    *(float2*)&g_agent[((size_t)b * ANUM_ + p) * C_ + 2 * c2] = o;
}

__global__ void zero_acc()
{
    const int i = blockIdx.x * 256 + threadIdx.x;
    if (i < B_ * NH_ * ANUM_ * HD_) g_num[i] = 0.f;
    if (i < B_ * NH_ * ANUM_)       g_den[i] = 0.f;
}

// ---------------- agent attention via tensor cores (validated R12/R13/R15) ------
#define AKROW 144u
#define AG_OFF  0u
#define W_OFF   9216u
#define KS_OFF  18432u
#define VS_OFF  36864u
#define DEN_OFF 55296u
#define AK_SMEM 55552

__global__ void __launch_bounds__(128)
agent_kv_mma()
{
    extern __shared__ char sm[];
    const uint32_t sb = smem_u32(sm);
    float* den_s = (float*)(sm + DEN_OFF);
    __half* ag16 = (__half*)(sm + AG_OFF);
    __half* Wsm  = (__half*)(sm + W_OFF);

    const int bh = blockIdx.x;
    const int part = blockIdx.y;
    const int b = bh >> 3, h = bh & 7;
    const int tid = threadIdx.x;
    const int wid = tid >> 5, lane = tid & 31;
    const int g = lane >> 2, t = lane & 3;
    const int wtok = wid * 16;
    const int wdim = wid * 16;

    for (int i = tid; i < 64 * 64; i += 128) {
        const int a = i >> 6, d = i & 63;
        float v = 0.f;
        if (a < ANUM_)
            v = g_agent[((size_t)(b * ANUM_ + a)) * C_ + h * HD_ + d] * SCALE_F;
        ag16[a * 72 + d] = __float2half(v);
    }
    if (tid < 64) den_s[tid] = 0.f;
    __syncthreads();

    const int aTile = lane >> 3;
    const uint32_t aLane =
        (uint32_t)(((aTile & 1) * 8 + (lane & 7)) * AKROW + (aTile >> 1) * 16);
    const uint32_t bLane =
        (uint32_t)((lane & 7) * AKROW + ((lane >> 3) & 1) * 16);

    uint32_t agF[4][4][4];
#pragma unroll
    for (int mf = 0; mf < 4; ++mf)
#pragma unroll
        for (int ks = 0; ks < 4; ++ks)
            ldsm4(agF[mf][ks], sb + AG_OFF + aLane + (uint32_t)(mf * 16) * AKROW + ks * 32u);

    const int ntok0 = part * 448;
    auto load_tile = [&](int tt) {
        const uint32_t buf = (uint32_t)(tt & 1) * 9216u;
#pragma unroll
        for (int it = 0; it < 4; ++it) {
            const int i = tid + it * 128;
            const int r = i >> 3, cch = i & 7;
            const __half* src =
                g_qkv16 + ((size_t)(b * N_ + ntok0 + tt * 64 + r)) * 1536 + 512 + h * HD_ + cch * 8;
            cp16(sb + KS_OFF + buf + (uint32_t)r * AKROW + cch * 16u, src);
            cp16(sb + VS_OFF + buf + (uint32_t)r * AKROW + cch * 16u, src + 512);
        }
        asm volatile("cp.async.commit_group;" ::: "memory");
    };

    float acc[4][2][4];
#pragma unroll
    for (int i = 0; i < 4; ++i)
#pragma unroll
        for (int j = 0; j < 2; ++j)
#pragma unroll
            for (int q = 0; q < 4; ++q) acc[i][j][q] = 0.f;

    load_tile(0);

    for (int tt = 0; tt < 7; ++tt) {
        asm volatile("cp.async.wait_group 0;" ::: "memory");
        __syncthreads();
        const uint32_t buf = (uint32_t)(tt & 1) * 9216u;

        float c1[4][2][4];
#pragma unroll
        for (int i = 0; i < 4; ++i)
#pragma unroll
            for (int j = 0; j < 2; ++j)
#pragma unroll
                for (int q = 0; q < 4; ++q) c1[i][j][q] = 0.f;

#pragma unroll
        for (int ks = 0; ks < 4; ++ks) {
            uint32_t kF[2][2];
#pragma unroll
            for (int nf = 0; nf < 2; ++nf)
                ldsm2(kF[nf], sb + KS_OFF + buf + bLane +
                      (uint32_t)(wtok + nf * 8) * AKROW + ks * 32u);
#pragma unroll
            for (int mf = 0; mf < 4; ++mf)
#pragma unroll
                for (int nf = 0; nf < 2; ++nf)
                    mma_f16(c1[mf][nf], agF[mf][ks], kF[nf]);
        }

        if (tt + 1 < 7) load_tile(tt + 1);
        else asm volatile("cp.async.commit_group;" ::: "memory");

#pragma unroll
        for (int mf = 0; mf < 4; ++mf) {
            float e[2][4];
#pragma unroll
            for (int nf = 0; nf < 2; ++nf)
#pragma unroll
                for (int q = 0; q < 4; ++q) e[nf][q] = fexp(c1[mf][nf][q]);
            float d0 = e[0][0] + e[0][1] + e[1][0] + e[1][1];
            float d1 = e[0][2] + e[0][3] + e[1][2] + e[1][3];
            d0 += __shfl_xor_sync(0xffffffff, d0, 1);
            d0 += __shfl_xor_sync(0xffffffff, d0, 2);
            d1 += __shfl_xor_sync(0xffffffff, d1, 1);
            d1 += __shfl_xor_sync(0xffffffff, d1, 2);
            const int rowA = mf * 16 + g, rowB = rowA + 8;
            if (t == 0) {
                atomicAdd(&den_s[rowA], d0);
                atomicAdd(&den_s[rowB], d1);
            }
#pragma unroll
            for (int nf = 0; nf < 2; ++nf) {
                const int col = wtok + nf * 8 + 2 * t;
                __half2 h0 = __floats2half2_rn(e[nf][0], e[nf][1]);
                __half2 h1 = __floats2half2_rn(e[nf][2], e[nf][3]);
                *(uint32_t*)&Wsm[rowA * 72 + col] = *(uint32_t*)&h0;
                *(uint32_t*)&Wsm[rowB * 72 + col] = *(uint32_t*)&h1;
            }
        }
        __syncthreads();

#pragma unroll
        for (int ks = 0; ks < 4; ++ks) {
            uint32_t vF[4];
            ldsm4t(vF, sb + VS_OFF + buf +
                   (uint32_t)(ks * 16 + (lane & 15)) * AKROW +
                   (uint32_t)(wdim + (lane >> 4) * 8) * 2u);
#pragma unroll
            for (int mf = 0; mf < 4; ++mf) {
                uint32_t wF[4];
                ldsm4(wF, sb + W_OFF + aLane + (uint32_t)(mf * 16) * AKROW + ks * 32u);
                mma_f16(acc[mf][0], wF, vF);
                mma_f16(acc[mf][1], wF, vF + 2);
            }
        }
        __syncthreads();
    }

    if (tid < ANUM_) atomicAdd(&g_den[bh * ANUM_ + tid], den_s[tid]);
#pragma unroll
    for (int mf = 0; mf < 4; ++mf) {
        const int rowA = mf * 16 + g, rowB = rowA + 8;
#pragma unroll
        for (int nf = 0; nf < 2; ++nf) {
            const int dim = wdim + nf * 8 + 2 * t;
            if (rowA < ANUM_) {
                float* p = &g_num[(((size_t)bh * ANUM_) + rowA) * HD_ + dim];
                atomicAdd(p, acc[mf][nf][0]);
                atomicAdd(p + 1, acc[mf][nf][1]);
            }
            if (rowB < ANUM_) {
                float* p = &g_num[(((size_t)bh * ANUM_) + rowB) * HD_ + dim];
                atomicAdd(p, acc[mf][nf][2]);
                atomicAdd(p + 1, acc[mf][nf][3]);
            }
        }
    }
}

// ---------------- q attention via tensor cores ----------------------------------
#define QA_AG   0u
#define QA_AV   9216u
#define QA_W    18432u
#define QA_Q    27648u
#define QA_DEN  46080u
#define QA_SMEM 47104

__global__ void __launch_bounds__(128)
q_attn_mma()
{
    extern __shared__ char sm[];
    const uint32_t sb = smem_u32(sm);
    __half* ag16 = (__half*)(sm + QA_AG);
    __half* av16 = (__half*)(sm + QA_AV);
    __half* Wsm  = (__half*)(sm + QA_W);
    float* den_s = (float*)(sm + QA_DEN);

    const int bh = blockIdx.x;
    const int part = blockIdx.y;
    const int b = bh >> 3, h = bh & 7;
    const int tid = threadIdx.x;
    const int wid = tid >> 5, lane = tid & 31;
    const int g = lane >> 2, t = lane & 3;
    const int wagent = wid * 16;
    const int wdim = wid * 16;

    for (int i = tid; i < 64 * 64; i += 128) {
        const int a = i >> 6, d = i & 63;
        float va = 0.f, vv = 0.f;
        if (a < ANUM_) {
            va = g_agent[((size_t)(b * ANUM_ + a)) * C_ + h * HD_ + d] * SCALE_F;
            vv = g_num[(((size_t)bh * ANUM_) + a) * HD_ + d] / g_den[bh * ANUM_ + a];
        }
        ag16[a * 72 + d] = __float2half(va);
        av16[a * 72 + d] = __float2half(vv);
    }
    __syncthreads();

    const int aTile = lane >> 3;
    const uint32_t aLane =
        (uint32_t)(((aTile & 1) * 8 + (lane & 7)) * AKROW + (aTile >> 1) * 16);
    const uint32_t bLane =
        (uint32_t)((lane & 7) * AKROW + ((lane >> 3) & 1) * 16);

    uint32_t agB[4][2][2];
#pragma unroll
    for (int ks = 0; ks < 4; ++ks)
#pragma unroll
        for (int nf = 0; nf < 2; ++nf)
            ldsm2(agB[ks][nf], sb + QA_AG + bLane +
                  (uint32_t)(wagent + nf * 8) * AKROW + ks * 32u);
    uint32_t avB[4][4];
#pragma unroll
    for (int ks = 0; ks < 4; ++ks)
        ldsm4t(avB[ks], sb + QA_AV +
               (uint32_t)(ks * 16 + (lane & 15)) * AKROW +
               (uint32_t)(wdim + (lane >> 4) * 8) * 2u);

    const int ntok0 = part * 448;
    auto load_tile = [&](int tt) {
        const uint32_t buf = (uint32_t)(tt & 1) * 9216u;
#pragma unroll
        for (int it = 0; it < 4; ++it) {
            const int i = tid + it * 128;
            const int r = i >> 3, cch = i & 7;
            const __half* src =
                g_qkv16 + ((size_t)(b * N_ + ntok0 + tt * 64 + r)) * 1536 + h * HD_ + cch * 8;
            cp16(sb + QA_Q + buf + (uint32_t)r * AKROW + cch * 16u, src);
        }
        asm volatile("cp.async.commit_group;" ::: "memory");
    };

    load_tile(0);

    for (int tt = 0; tt < 7; ++tt) {
        asm volatile("cp.async.wait_group 0;" ::: "memory");
        __syncthreads();
        const uint32_t buf = (uint32_t)(tt & 1) * 9216u;

        float c1[4][2][4];
#pragma unroll
        for (int i = 0; i < 4; ++i)
#pragma unroll
            for (int j = 0; j < 2; ++j)
#pragma unroll
                for (int q = 0; q < 4; ++q) c1[i][j][q] = 0.f;

#pragma unroll
        for (int ks = 0; ks < 4; ++ks) {
            uint32_t qf[4][4];
#pragma unroll
            for (int mf = 0; mf < 4; ++mf)
                ldsm4(qf[mf], sb + QA_Q + buf + aLane +
                      (uint32_t)(mf * 16) * AKROW + ks * 32u);
#pragma unroll
            for (int mf = 0; mf < 4; ++mf)
#pragma unroll
                for (int nf = 0; nf < 2; ++nf)
                    mma_f16(c1[mf][nf], qf[mf], agB[ks][nf]);
        }

        if (tt + 1 < 7) load_tile(tt + 1);
        else asm volatile("cp.async.commit_group;" ::: "memory");

#pragma unroll
        for (int mf = 0; mf < 4; ++mf) {
            float e[2][4];
#pragma unroll
            for (int nf = 0; nf < 2; ++nf)
#pragma unroll
                for (int q = 0; q < 4; ++q) e[nf][q] = fexp(c1[mf][nf][q]);
            float d0 = e[0][0] + e[0][1] + e[1][0] + e[1][1];
            float d1 = e[0][2] + e[0][3] + e[1][2] + e[1][3];
            d0 += __shfl_xor_sync(0xffffffff, d0, 1);
            d0 += __shfl_xor_sync(0xffffffff, d0, 2);
            d1 += __shfl_xor_sync(0xffffffff, d1, 1);
            d1 += __shfl_xor_sync(0xffffffff, d1, 2);
            const int rowA = mf * 16 + g, rowB = rowA + 8;
            if (t == 0) {
                den_s[wid * 64 + rowA] = d0;
                den_s[wid * 64 + rowB] = d1;
            }
#pragma unroll
            for (int nf = 0; nf < 2; ++nf) {
                const int col = wagent + nf * 8 + 2 * t;
                __half2 h0 = __floats2half2_rn(e[nf][0], e[nf][1]);
                __half2 h1 = __floats2half2_rn(e[nf][2], e[nf][3]);
                *(uint32_t*)&Wsm[rowA * 72 + col] = *(uint32_t*)&h0;
                *(uint32_t*)&Wsm[rowB * 72 + col] = *(uint32_t*)&h1;
            }
        }
        __syncthreads();

        float acc[4][2][4];
#pragma unroll
        for (int i = 0; i < 4; ++i)
#pragma unroll
            for (int j = 0; j < 2; ++j)
#pragma unroll
                for (int q = 0; q < 4; ++q) acc[i][j][q] = 0.f;

#pragma unroll
        for (int ks = 0; ks < 4; ++ks) {
#pragma unroll
            for (int mf = 0; mf < 4; ++mf) {
                uint32_t wF[4];
                ldsm4(wF, sb + QA_W + aLane + (uint32_t)(mf * 16) * AKROW + ks * 32u);
                mma_f16(acc[mf][0], wF, avB[ks]);
                mma_f16(acc[mf][1], wF, avB[ks] + 2);
            }
        }

        // epilogue: normalize (den - 15 pad correction), write fp16
#pragma unroll
        for (int mf = 0; mf < 4; ++mf) {
            const int rowA = mf * 16 + g, rowB = rowA + 8;
            const float invA = 1.f / (den_s[rowA] + den_s[64 + rowA] +
                                      den_s[128 + rowA] + den_s[192 + rowA] - 15.f);
            const float invB = 1.f / (den_s[rowB] + den_s[64 + rowB] +
                                      den_s[128 + rowB] + den_s[192 + rowB] - 15.f);
            const long tokA = (long)(b * N_ + ntok0 + tt * 64 + rowA);
            const long tokB = (long)(b * N_ + ntok0 + tt * 64 + rowB);
#pragma unroll
            for (int nf = 0; nf < 2; ++nf) {
                const int col = h * HD_ + wdim + nf * 8 + 2 * t;
                __half2 h0 = __floats2half2_rn(acc[mf][nf][0] * invA, acc[mf][nf][1] * invA);
                __half2 h1 = __floats2half2_rn(acc[mf][nf][2] * invB, acc[mf][nf][3] * invB);
                *(uint32_t*)&g_o16[tokA * C_ + col] = *(uint32_t*)&h0;
                *(uint32_t*)&g_o16[tokB * C_ + col] = *(uint32_t*)&h1;
            }
        }
        __syncthreads();
    }
}

// ---------------- depthwise 3x3 conv on v16, += into g_o16 (with bias) ----------
__global__ void __launch_bounds__(256)
dwc16(const float* __restrict__ w, const float* __restrict__ bias)
{
    __shared__ float ws[C_ * 9];
    __shared__ float bs[C_];
    const int b = blockIdx.x, y = blockIdx.y;
    const int tid = threadIdx.x;
    for (int i = tid; i < C_ * 9; i += 256) ws[i] = w[i];
    for (int i = tid; i < C_; i += 256) bs[i] = bias[i];
    __syncthreads();

    for (int i = tid; i < H_ * 64; i += 256) {
        const int x = i >> 6;
        const int c8 = (i & 63) * 8;
        float a[8];
#pragma unroll
        for (int j = 0; j < 8; ++j) a[j] = bs[c8 + j];

#pragma unroll
        for (int ky = 0; ky < 3; ++ky) {
            const int yy = y + ky - 1;
            if (yy < 0 || yy >= H_) continue;
#pragma unroll
            for (int kx = 0; kx < 3; ++kx) {
                const int xx = x + kx - 1;
                if (xx < 0 || xx >= H_) continue;
                const int tap = ky * 3 + kx;
                const uint4 v = *(const uint4*)&g_qkv16[((size_t)(b * N_ + yy * H_ + xx)) * 1536 + 1024 + c8];
                const __half2* vh = (const __half2*)&v;
#pragma unroll
                for (int j2 = 0; j2 < 4; ++j2) {
                    const float2 f = __half22float2(vh[j2]);
                    a[j2 * 2 + 0] += f.x * ws[(c8 + j2 * 2 + 0) * 9 + tap];
                    a[j2 * 2 + 1] += f.y * ws[(c8 + j2 * 2 + 1) * 9 + tap];
                }
            }
        }

        __half* op = &g_o16[((size_t)(b * N_ + y * H_ + x)) * C_ + c8];
        uint4 o = *(uint4*)op;
        __half2* oh = (__half2*)&o;
#pragma unroll
        for (int j2 = 0; j2 < 4; ++j2) {
            float2 f = __half22float2(oh[j2]);
            f.x += a[j2 * 2 + 0];
            f.y += a[j2 * 2 + 1];
            oh[j2] = __floats2half2_rn(f.x, f.y);
        }
        *(uint4*)op = o;
    }
}

// ---------------- launch ----------------
extern "C" void kernel_launch(void* const* d_in, const int* in_sizes, int n_in,
                              void* d_out, int out_size)
{
    const float* x      = (const float*)d_in[0];
    const float* qkv_w  = (const float*)d_in[1];
    const float* proj_w = (const float*)d_in[2];
    const float* proj_b = (const float*)d_in[3];
    const float* dwc_w  = (const float*)d_in[4];
    const float* dwc_b  = (const float*)d_in[5];
    float* out = (float*)d_out;

    __half *p_qkv16 = nullptr, *p_x16 = nullptr, *p_o16 = nullptr, *p_w16 = nullptr;
    cudaGetSymbolAddress((void**)&p_qkv16, g_qkv16);
    cudaGetSymbolAddress((void**)&p_x16, g_x16);
    cudaGetSymbolAddress((void**)&p_o16, g_o16);
    cudaGetSymbolAddress((void**)&p_w16, g_w16);

    cudaFuncSetAttribute(gemm_h, cudaFuncAttributeMaxDynamicSharedMemorySize, GH_SMEM);
    cudaFuncSetAttribute(agent_kv_mma, cudaFuncAttributeMaxDynamicSharedMemorySize, AK_SMEM);
    cudaFuncSetAttribute(q_attn_mma, cudaFuncAttributeMaxDynamicSharedMemorySize, QA_SMEM);

    // 0. pre-convert inputs to fp16
    cvt_f16<<<(M_ * C_ / 4 + 255) / 256, 256>>>(x, p_x16, M_ * C_ / 4);
    cvt_f16<<<(1536 * 512 / 4 + 255) / 256, 256>>>(qkv_w, p_w16, 1536 * 512 / 4);
    cvt_f16<<<(512 * 512 / 4 + 255) / 256, 256>>>(proj_w, p_w16 + 1536 * 512, 512 * 512 / 4);

    // 1. QKV projection -> g_qkv16 (fp16 only)
    gemm_h<<<dim3(1536 / 128, M_ / 128), 256, GH_SMEM>>>(p_x16, p_w16, nullptr, p_qkv16, nullptr, 512, 512, 512, 1536);
    // 2. zero agent-attn accumulators
    zero_acc<<<(B_ * NH_ * ANUM_ * HD_ + 255) / 256, 256>>>();
    // 3. agent pooling (fp16 source)
    pool_q16<<<B_ * ANUM_, 256>>>();
    // 4. agent attention (tensor cores)
    agent_kv_mma<<<dim3(B_ * NH_, 7), 128, AK_SMEM>>>();
    // 5. q attention (tensor cores) -> g_o16
    q_attn_mma<<<dim3(B_ * NH_, 7), 128, QA_SMEM>>>();
    // 6. depthwise conv on v16, += into g_o16 (with bias)
    dwc16<<<dim3(B_, H_), 256>>>(dwc_w, dwc_b);
    // 7. output projection (+bias) -> d_out (fp32)
    gemm_h<<<dim3(512 / 128, M_ / 128), 256, GH_SMEM>>>(p_o16, p_w16 + 1536 * 512, out, nullptr, proj_b, 512, 512, 512, 512);
}